// round 7
// baseline (speedup 1.0000x reference)
#include <cuda_runtime.h>
#include <stdint.h>

// out[i, 0:8] = params[idx[i]] * xs[i, 0:8]
// xs: float32 [N, 8]; idx: int32 [N]; params: float32 [V]; out: float32 [N, 8]
// N = 4194304, V = 1048576.
//
// TMA bulk pipeline: streams (xs in, out) ride cp.async.bulk (no L1tex, big
// DRAM bursts); only the random param gather uses LDG (L2-resident table).
// 2-stage double buffer per CTA, compute in-place in smem, bulk store out.

#define N_ROWS        4194304
#define TILE_ROWS     512
#define TILE_X4       (TILE_ROWS * 2)        // 1024 float4 per tile
#define TILE_XS_BYTES (TILE_X4 * 16)         // 16384
#define TILE_IDX_BYTES (TILE_ROWS * 4)       // 2048
#define STAGES        2
#define THREADS       256
#define ITEMS_PER_THR (TILE_X4 / THREADS)    // 4
#define NUM_TILES     (N_ROWS / TILE_ROWS)   // 8192
#define TILES_PER_CTA 4
#define BLOCKS        (NUM_TILES / TILES_PER_CTA)  // 2048

__device__ __forceinline__ uint32_t smem_u32(const void* p) {
    return (uint32_t)__cvta_generic_to_shared(p);
}

__device__ __forceinline__ void mbar_init(uint32_t mbar, uint32_t count) {
    asm volatile("mbarrier.init.shared.b64 [%0], %1;" :: "r"(mbar), "r"(count) : "memory");
}
__device__ __forceinline__ void mbar_expect_tx(uint32_t mbar, uint32_t bytes) {
    asm volatile("mbarrier.arrive.expect_tx.shared.b64 _, [%0], %1;"
                 :: "r"(mbar), "r"(bytes) : "memory");
}
__device__ __forceinline__ void mbar_wait(uint32_t mbar, uint32_t parity) {
    asm volatile(
        "{\n\t"
        ".reg .pred P;\n\t"
        "WAIT_%=:\n\t"
        "mbarrier.try_wait.parity.shared.b64 P, [%0], %1, 0x989680;\n\t"
        "@P bra.uni DONE_%=;\n\t"
        "bra.uni WAIT_%=;\n\t"
        "DONE_%=:\n\t"
        "}"
        :: "r"(mbar), "r"(parity) : "memory");
}
__device__ __forceinline__ void bulk_load(uint32_t dst_smem, const void* src,
                                          uint32_t bytes, uint32_t mbar) {
    asm volatile(
        "cp.async.bulk.shared::cluster.global.mbarrier::complete_tx::bytes "
        "[%0], [%1], %2, [%3];"
        :: "r"(dst_smem), "l"(src), "r"(bytes), "r"(mbar) : "memory");
}
__device__ __forceinline__ void bulk_store(void* dst, uint32_t src_smem, uint32_t bytes) {
    asm volatile(
        "cp.async.bulk.global.shared::cta.bulk_group [%0], [%1], %2;"
        :: "l"(dst), "r"(src_smem), "r"(bytes) : "memory");
}

__global__ __launch_bounds__(THREADS) void gather_mul_tma_kernel(
    const float4* __restrict__ xs,     // [2N] float4
    const int*    __restrict__ idx,    // [N]
    const float*  __restrict__ params, // [V]
    float4*       __restrict__ out)    // [2N] float4
{
    __shared__ float4   s_xs[STAGES][TILE_X4];    // 32 KB
    __shared__ int      s_idx[STAGES][TILE_ROWS]; // 4 KB
    __shared__ uint64_t s_mbar[STAGES];

    const int tid = threadIdx.x;
    const bool leader = (tid == 0);
    const int tile0 = blockIdx.x * TILES_PER_CTA;

    uint32_t mbar_a[STAGES];
#pragma unroll
    for (int s = 0; s < STAGES; s++) mbar_a[s] = smem_u32(&s_mbar[s]);

    if (leader) {
#pragma unroll
        for (int s = 0; s < STAGES; s++) mbar_init(mbar_a[s], 1);
    }
    __syncthreads();

    // Prologue: prefetch first STAGES tiles.
    if (leader) {
#pragma unroll
        for (int s = 0; s < STAGES; s++) {
            const int t = tile0 + s;
            mbar_expect_tx(mbar_a[s], TILE_XS_BYTES + TILE_IDX_BYTES);
            bulk_load(smem_u32(&s_xs[s][0]),  xs  + (size_t)t * TILE_X4,
                      TILE_XS_BYTES, mbar_a[s]);
            bulk_load(smem_u32(&s_idx[s][0]), idx + (size_t)t * TILE_ROWS,
                      TILE_IDX_BYTES, mbar_a[s]);
        }
    }

    int ph[STAGES];
#pragma unroll
    for (int s = 0; s < STAGES; s++) ph[s] = 0;

    for (int i = 0; i < TILES_PER_CTA; i++) {
        const int st = i % STAGES;
        const int tile = tile0 + i;

        mbar_wait(mbar_a[st], ph[st]);
        ph[st] ^= 1;

        // Compute in-place: item m = tid + k*THREADS; row = m >> 1.
        int   j[ITEMS_PER_THR];
#pragma unroll
        for (int k = 0; k < ITEMS_PER_THR; k++)
            j[k] = s_idx[st][(tid + k * THREADS) >> 1];

        float p[ITEMS_PER_THR];
#pragma unroll
        for (int k = 0; k < ITEMS_PER_THR; k++)
            p[k] = __ldcg(params + j[k]);

#pragma unroll
        for (int k = 0; k < ITEMS_PER_THR; k++) {
            const int m = tid + k * THREADS;
            float4 v = s_xs[st][m];
            v.x *= p[k]; v.y *= p[k]; v.z *= p[k]; v.w *= p[k];
            s_xs[st][m] = v;
        }
        __syncthreads();

        if (leader) {
            asm volatile("fence.proxy.async;" ::: "memory");
            bulk_store(out + (size_t)tile * TILE_X4, smem_u32(&s_xs[st][0]),
                       TILE_XS_BYTES);
            asm volatile("cp.async.bulk.commit_group;" ::: "memory");

            const int ni = i + STAGES;
            if (ni < TILES_PER_CTA) {
                // All committed stores must finish READING smem before refill.
                asm volatile("cp.async.bulk.wait_group.read 0;" ::: "memory");
                const int t = tile0 + ni;
                mbar_expect_tx(mbar_a[st], TILE_XS_BYTES + TILE_IDX_BYTES);
                bulk_load(smem_u32(&s_xs[st][0]),  xs  + (size_t)t * TILE_X4,
                          TILE_XS_BYTES, mbar_a[st]);
                bulk_load(smem_u32(&s_idx[st][0]), idx + (size_t)t * TILE_ROWS,
                          TILE_IDX_BYTES, mbar_a[st]);
            }
        }
    }

    // Drain outstanding stores fully before exit.
    if (leader)
        asm volatile("cp.async.bulk.wait_group 0;" ::: "memory");
}

extern "C" void kernel_launch(void* const* d_in, const int* in_sizes, int n_in,
                              void* d_out, int out_size)
{
    const float4* xs     = (const float4*)d_in[0];
    const int*    idx    = (const int*)d_in[1];
    const float*  params = (const float*)d_in[2];
    float4*       out    = (float4*)d_out;

    gather_mul_tma_kernel<<<BLOCKS, THREADS>>>(xs, idx, params, out);
}